// round 15
// baseline (speedup 1.0000x reference)
#include <cuda_runtime.h>
#include <cuda_fp16.h>
#include <cstdint>

// Problem constants (target: [B, T, L] float32)
constexpr int B_ = 32;
constexpr int T_ = 8;
constexpr int L_ = 256;

// GEMM formulation per (b, t):
//   S[l, k] = x[k - l]  (0 for k < l)     -- Toeplitz: never materialized.
//   A[m, k] = x[k] * S[m, k]              -- built in registers (hmul2)
//   TM[m, l2] = sum_k A[m,k] * S[l2,k]    -- mma.sync m16n8k16 f16 -> f32
//
// ldmatrix reads directly from 8 shift-copies of the padded fp16 signal
// (copy_s[i] = x_pad[i+s]) at bases E_s = 1168*s (+112 for s=0): every 8-row
// ldmatrix phase is a perfect bank-group permutation (conflict-free).
//
// R15: OCCUPANCY 3 / SINGLE WAVE. R12 structure (2 rotating copy sets =
// 34.8KB smem, 32x32 warp tiles = 85 regs) is the only shape that fits
// 3 CTAs/SM — lift __launch_bounds__ to (256,3). 148x3 = 444 slots >= 320
// CTAs -> whole grid resident in ONE wave (no straggler round), and 24
// warps/SM hides the LDSM->HMMA latency that has pinned tensor% ~40-53.
// Symmetry (lower-triangle 64x64 tiles, 10/batch) + mirror stores kept.

__device__ __forceinline__ uint32_t smem_u32(const void* p) {
    uint32_t a;
    asm("{ .reg .u64 t; cvta.to.shared.u64 t, %1; cvt.u32.u64 %0, t; }" : "=r"(a) : "l"(p));
    return a;
}
__device__ __forceinline__ uint32_t hmul2(uint32_t a, uint32_t b) {
    uint32_t d;
    asm("mul.rn.f16x2 %0, %1, %2;" : "=r"(d) : "r"(a), "r"(b));
    return d;
}
__device__ __forceinline__ void ldsm4(uint32_t& r0, uint32_t& r1, uint32_t& r2,
                                      uint32_t& r3, uint32_t addr) {
    asm volatile("ldmatrix.sync.aligned.m8n8.x4.shared.b16 {%0,%1,%2,%3}, [%4];"
                 : "=r"(r0), "=r"(r1), "=r"(r2), "=r"(r3) : "r"(addr));
}
__device__ __forceinline__ void mma16816(float* d, const uint32_t* a,
                                         uint32_t b0, uint32_t b1) {
    asm volatile(
        "mma.sync.aligned.m16n8k16.row.col.f32.f16.f16.f32 "
        "{%0,%1,%2,%3}, {%4,%5,%6,%7}, {%8,%9}, {%0,%1,%2,%3};"
        : "+f"(d[0]), "+f"(d[1]), "+f"(d[2]), "+f"(d[3])
        : "r"(a[0]), "r"(a[1]), "r"(a[2]), "r"(a[3]), "r"(b0), "r"(b1));
}

// copy base within a copy set (bytes): E_s = 1168*s + (s==0 ? 112 : 0)
__device__ __forceinline__ uint32_t copy_base(int s) {
    return 1168u * s + (s == 0 ? 112u : 0u);
}

constexpr int COPYSET  = 9216;                    // bytes per t-group copy set
constexpr int SM_MERGE = 2 * COPYSET;             // 18432
constexpr int SM_TOTAL = SM_MERGE + 4 * 1024 * 4; // + 16KB merge = 34816

__global__ __launch_bounds__(256, 3)
void bispectrum_mma_kernel(const float* __restrict__ tgt, float* __restrict__ out)
{
    extern __shared__ __align__(16) unsigned char smb[];
    const uint32_t sB = smem_u32(smb);
    float* mg = (float*)(smb + SM_MERGE);

    const int tid  = threadIdx.x;
    const int w    = tid >> 5;
    const int lane = tid & 31;
    const int g    = lane >> 2;     // 0..7
    const int q    = lane & 3;      // 0..3

    // block -> (batch, lower-triangle tile (i_, j_)), 64x64 tiles, i_ >= j_
    const int bid = blockIdx.x;
    const int b   = bid / 10;
    const int tri = bid - b * 10;
    const int i_  = (tri >= 6) ? 3 : (tri >= 3) ? 2 : (tri >= 1) ? 1 : 0;
    const int j_  = tri - i_ * (i_ + 1) / 2;
    const int m0  = i_ * 64;
    const int n0  = j_ * 64;

    const int sw   = w & 3;                    // spatial warp (2x2)
    const int grp  = w >> 2;                   // t-group (0: t 0-3, 1: t 4-7)
    const int mBase = m0 + 32 * (sw >> 1);
    const int nBase = n0 + 32 * (sw & 1);
    const uint32_t cOff = (uint32_t)grp * COPYSET;

    // zero both copy sets once (left pads stay zero forever)
    for (int i = tid; i < 2 * COPYSET / 4; i += 256)
        *(uint32_t*)(smb + 4 * i) = 0u;

    float acc[2][4][4];
#pragma unroll
    for (int mt = 0; mt < 2; mt++)
#pragma unroll
        for (int j = 0; j < 4; j++)
#pragma unroll
            for (int c = 0; c < 4; c++) acc[mt][j][c] = 0.0f;

    // ---- per-lane ldmatrix base addresses (constant across t, += 32B per kt)
    // row u, col-shift cs (halfs): addr = E(s) + (256 + cs - u - s)*2, s=(-u)&7
    uint32_t aBase[2], bBase[2];
#pragma unroll
    for (int mt = 0; mt < 2; mt++) {
        const int u  = mBase + mt * 16 + (lane & 15);
        const int cs = (lane & 16) ? 8 : 0;
        const int s  = (-u) & 7;
        aBase[mt] = sB + cOff + copy_base(s) + (uint32_t)(256 + cs - u - s) * 2;
    }
#pragma unroll
    for (int nb = 0; nb < 2; nb++) {
        const int u  = nBase + nb * 16 + (lane & 7) + ((lane & 16) ? 8 : 0);
        const int cs = (lane & 8) ? 8 : 0;
        const int s  = (-u) & 7;
        bBase[nb] = sB + cOff + copy_base(s) + (uint32_t)(256 + cs - u - s) * 2;
    }
    // scalar k broadcast from copy 0 of this group's set: half2 at 256+16kt+2q
    const uint32_t xkA = sB + cOff + 112u + 512u + 4u * q;   // += 32 per kt

    for (int tt = 0; tt < 4; tt++) {
        __syncthreads();                   // previous MMA phase done reading copies
        // every thread writes its element into BOTH t-group copy sets
#pragma unroll
        for (int wg = 0; wg < 2; wg++) {
            const __half h = __float2half_rn(
                tgt[(b * T_ + tt + 4 * wg) * L_ + tid]);
#pragma unroll
            for (int s = 0; s < 8; s++)
                *(__half*)(smb + wg * COPYSET + copy_base(s) +
                           (uint32_t)(256 + tid - s) * 2) = h;
        }
        __syncthreads();

        // ---- MMA phase: K = 256 in 16 steps of k16 ----
#pragma unroll 4
        for (int kt = 0; kt < 16; kt++) {
            const uint32_t koff = (uint32_t)kt * 32u;
            uint32_t xk0, xk1;
            asm volatile("ld.shared.b32 %0, [%1];" : "=r"(xk0) : "r"(xkA + koff));
            asm volatile("ld.shared.b32 %0, [%1];" : "=r"(xk1) : "r"(xkA + koff + 16));

            uint32_t Af[2][4];
#pragma unroll
            for (int mt = 0; mt < 2; mt++) {
                uint32_t a0, a1, a2, a3;
                ldsm4(a0, a1, a2, a3, aBase[mt] + koff);
                Af[mt][0] = hmul2(a0, xk0);
                Af[mt][1] = hmul2(a1, xk0);
                Af[mt][2] = hmul2(a2, xk1);
                Af[mt][3] = hmul2(a3, xk1);
            }
#pragma unroll
            for (int nb = 0; nb < 2; nb++) {
                uint32_t b0, b1, b2, b3;
                ldsm4(b0, b1, b2, b3, bBase[nb] + koff);
#pragma unroll
                for (int mt = 0; mt < 2; mt++) {
                    mma16816(acc[mt][2 * nb],     Af[mt], b0, b1);
                    mma16816(acc[mt][2 * nb + 1], Af[mt], b2, b3);
                }
            }
        }
    }

    // ---- merge t-groups (intra-CTA) + epilogue ----
    __syncthreads();
    if (grp == 1) {
        float* mt_ = mg + sw * 1024 + lane;     // stride 32: conflict-free
#pragma unroll
        for (int mt = 0; mt < 2; mt++)
#pragma unroll
            for (int j = 0; j < 4; j++)
#pragma unroll
                for (int c = 0; c < 4; c++)
                    mt_[((mt * 4 + j) * 4 + c) * 32] = acc[mt][j][c];
    }
    __syncthreads();
    if (grp == 0) {
        const float scale = 1.0f / (float)(T_ * L_);
        const float* mt_ = mg + sw * 1024 + lane;
        float* ob = out + (size_t)b * L_ * L_;
        const bool mirror = (i_ != j_);
#pragma unroll
        for (int mt = 0; mt < 2; mt++) {
            const int m = mBase + mt * 16 + g;
#pragma unroll
            for (int j = 0; j < 4; j++) {
                const int n = nBase + 8 * j + 2 * q;
                const int i0 = ((mt * 4 + j) * 4) * 32;
                float2 v0, v1;
                v0.x = (acc[mt][j][0] + mt_[i0])      * scale;
                v0.y = (acc[mt][j][1] + mt_[i0 + 32]) * scale;
                v1.x = (acc[mt][j][2] + mt_[i0 + 64]) * scale;
                v1.y = (acc[mt][j][3] + mt_[i0 + 96]) * scale;
                *(float2*)&ob[(size_t)m * L_ + n]       = v0;
                *(float2*)&ob[(size_t)(m + 8) * L_ + n] = v1;
                if (mirror) {   // TM[n, m] = TM[m, n]
                    ob[(size_t)n * L_ + m]           = v0.x;
                    ob[(size_t)(n + 1) * L_ + m]     = v0.y;
                    ob[(size_t)n * L_ + m + 8]       = v1.x;
                    ob[(size_t)(n + 1) * L_ + m + 8] = v1.y;
                }
            }
        }
    }
}

extern "C" void kernel_launch(void* const* d_in, const int* in_sizes, int n_in,
                              void* d_out, int out_size)
{
    const float* tgt = (const float*)d_in[0];
    float* out = (float*)d_out;

    cudaFuncSetAttribute(bispectrum_mma_kernel,
                         cudaFuncAttributeMaxDynamicSharedMemorySize, SM_TOTAL);

    bispectrum_mma_kernel<<<320, 256, SM_TOTAL>>>(tgt, out);

    // Reference returns (source, target): echo target after source if the
    // output buffer holds both.
    const long long src_elems = (long long)B_ * L_ * L_;        // 2,097,152
    const long long tgt_elems = (long long)B_ * T_ * L_;        // 65,536
    if ((long long)out_size >= src_elems + tgt_elems) {
        cudaMemcpyAsync(out + src_elems, tgt, sizeof(float) * tgt_elems,
                        cudaMemcpyDeviceToDevice);
    }
}

// round 17
// speedup vs baseline: 1.0847x; 1.0847x over previous
#include <cuda_runtime.h>
#include <cuda_fp16.h>
#include <cstdint>

// Problem constants (target: [B, T, L] float32)
constexpr int B_ = 32;
constexpr int T_ = 8;
constexpr int L_ = 256;

// GEMM formulation per (b, t):
//   S[l, k] = x[k - l]  (0 for k < l)     -- Toeplitz: never materialized.
//   A[m, k] = x[k] * S[m, k]              -- built in registers (hmul2)
//   TM[m, l2] = sum_k A[m,k] * S[l2,k]    -- mma.sync m16n8k16 f16 -> f32
//
// ldmatrix reads directly from 8 shift-copies of the padded fp16 signal
// (copy_s[i] = x_pad[i+s]) at bases E_s = 1168*s (+112 for s=0): every 8-row
// ldmatrix phase is a perfect bank-group permutation (conflict-free).
//
// R17 = R16 with the epilogue bug fixed (merge loop is 4 x 256 = 1024
// outputs for a 32x32 tile, NOT 16 x 256 — the r>=4 iterations aliased the
// same (m,n) decode and overwrote results with OOB-smem garbage).
//
// Design: task = one 32x32 lower-triangle tile, full t range -> 1152 CTAs
// (work-stealing erases per-SM imbalance). CTA: 256 thr = 8 warps = one
// warp per t (own copy set, zero barriers in MMA loop). Merge buffer reuses
// dead copy-set smem -> 72KB total -> 3 CTAs/SM. Work = 36/64 of full.

__device__ __forceinline__ uint32_t smem_u32(const void* p) {
    uint32_t a;
    asm("{ .reg .u64 t; cvta.to.shared.u64 t, %1; cvt.u32.u64 %0, t; }" : "=r"(a) : "l"(p));
    return a;
}
__device__ __forceinline__ uint32_t hmul2(uint32_t a, uint32_t b) {
    uint32_t d;
    asm("mul.rn.f16x2 %0, %1, %2;" : "=r"(d) : "r"(a), "r"(b));
    return d;
}
__device__ __forceinline__ void ldsm4(uint32_t& r0, uint32_t& r1, uint32_t& r2,
                                      uint32_t& r3, uint32_t addr) {
    asm volatile("ldmatrix.sync.aligned.m8n8.x4.shared.b16 {%0,%1,%2,%3}, [%4];"
                 : "=r"(r0), "=r"(r1), "=r"(r2), "=r"(r3) : "r"(addr));
}
__device__ __forceinline__ void mma16816(float* d, const uint32_t* a,
                                         uint32_t b0, uint32_t b1) {
    asm volatile(
        "mma.sync.aligned.m16n8k16.row.col.f32.f16.f16.f32 "
        "{%0,%1,%2,%3}, {%4,%5,%6,%7}, {%8,%9}, {%0,%1,%2,%3};"
        : "+f"(d[0]), "+f"(d[1]), "+f"(d[2]), "+f"(d[3])
        : "r"(a[0]), "r"(a[1]), "r"(a[2]), "r"(a[3]), "r"(b0), "r"(b1));
}

// copy base within a copy set (bytes): E_s = 1168*s + (s==0 ? 112 : 0)
__device__ __forceinline__ uint32_t copy_base(int s) {
    return 1168u * s + (s == 0 ? 112u : 0u);
}

constexpr int COPYSET  = 9216;            // bytes per copy set (one t)
constexpr int SM_TOTAL = 8 * COPYSET;     // 73728; merge buffer reuses this

__global__ __launch_bounds__(256, 3)
void bispectrum_mma_kernel(const float* __restrict__ tgt, float* __restrict__ out)
{
    extern __shared__ __align__(16) unsigned char smb[];
    const uint32_t sB = smem_u32(smb);
    float* mg = (float*)smb;               // merge buffer (reuses copy sets)

    const int tid  = threadIdx.x;
    const int w    = tid >> 5;             // warp = t index (0..7)
    const int lane = tid & 31;
    const int q    = lane & 3;             // 0..3

    // task -> (batch, lower-triangle 32x32 tile (i_, j_)), i_ >= j_
    const int task = blockIdx.x;
    const int b    = task / 36;
    int rem = task - b * 36;
    int i_ = 0;
#pragma unroll
    for (int r = 1; r < 8; r++) if (rem >= r * (r + 1) / 2) i_ = r;
    const int j_ = rem - i_ * (i_ + 1) / 2;
    const int m0 = i_ * 32;
    const int n0 = j_ * 32;

    const uint32_t cOff = (uint32_t)w * COPYSET;   // this warp's copy set

    // each thread loads its signal element for all 8 t (MLP-overlapped)
    float v[8];
#pragma unroll
    for (int u = 0; u < 8; u++) v[u] = tgt[(b * T_ + u) * L_ + tid];

    // zero all 8 copy sets (left pads stay zero), then build them
    for (int i = tid; i < 8 * COPYSET / 4; i += 256)
        *(uint32_t*)(smb + 4 * i) = 0u;
    __syncthreads();
#pragma unroll
    for (int u = 0; u < 8; u++) {          // set u holds t = u
        const __half h = __float2half_rn(v[u]);
#pragma unroll
        for (int s = 0; s < 8; s++)
            *(__half*)(smb + u * COPYSET + copy_base(s) +
                       (uint32_t)(256 + tid - s) * 2) = h;
    }
    __syncthreads();

    float acc[2][4][4];
#pragma unroll
    for (int mt = 0; mt < 2; mt++)
#pragma unroll
        for (int j = 0; j < 4; j++)
#pragma unroll
            for (int c = 0; c < 4; c++) acc[mt][j][c] = 0.0f;

    // ---- per-lane ldmatrix base addresses (+= 32B per kt) ----
    // row u, col-shift cs (halfs): addr = E(s) + (256 + cs - u - s)*2, s=(-u)&7
    uint32_t aBase[2], bBase[2];
#pragma unroll
    for (int mt = 0; mt < 2; mt++) {
        const int u  = m0 + mt * 16 + (lane & 15);
        const int cs = (lane & 16) ? 8 : 0;
        const int s  = (-u) & 7;
        aBase[mt] = sB + cOff + copy_base(s) + (uint32_t)(256 + cs - u - s) * 2;
    }
#pragma unroll
    for (int nb = 0; nb < 2; nb++) {
        const int u  = n0 + nb * 16 + (lane & 7) + ((lane & 16) ? 8 : 0);
        const int cs = (lane & 8) ? 8 : 0;
        const int s  = (-u) & 7;
        bBase[nb] = sB + cOff + copy_base(s) + (uint32_t)(256 + cs - u - s) * 2;
    }
    const uint32_t xkA = sB + cOff + 112u + 512u + 4u * q;   // += 32 per kt

    // ---- MMA loop: 16 kt steps, one t per warp, NO barriers ----
#pragma unroll 4
    for (int kt = 0; kt < 16; kt++) {
        const uint32_t koff = (uint32_t)kt * 32u;
        uint32_t xk0, xk1;
        asm volatile("ld.shared.b32 %0, [%1];" : "=r"(xk0) : "r"(xkA + koff));
        asm volatile("ld.shared.b32 %0, [%1];" : "=r"(xk1) : "r"(xkA + koff + 16));

        uint32_t Af[2][4];
#pragma unroll
        for (int mt = 0; mt < 2; mt++) {
            uint32_t a0, a1, a2, a3;
            ldsm4(a0, a1, a2, a3, aBase[mt] + koff);
            Af[mt][0] = hmul2(a0, xk0);
            Af[mt][1] = hmul2(a1, xk0);
            Af[mt][2] = hmul2(a2, xk1);
            Af[mt][3] = hmul2(a3, xk1);
        }
#pragma unroll
        for (int nb = 0; nb < 2; nb++) {
            uint32_t b0, b1, b2, b3;
            ldsm4(b0, b1, b2, b3, bBase[nb] + koff);
#pragma unroll
            for (int mt = 0; mt < 2; mt++) {
                mma16816(acc[mt][2 * nb],     Af[mt], b0, b1);
                mma16816(acc[mt][2 * nb + 1], Af[mt], b2, b3);
            }
        }
    }

    // ---- merge 8 t-partials (copy sets dead -> reuse smem) + epilogue ----
    __syncthreads();                        // all warps done with copy sets
    {
        float* mt_ = mg + w * 1024 + lane;  // stride 32: conflict-free
#pragma unroll
        for (int mt = 0; mt < 2; mt++)
#pragma unroll
            for (int j = 0; j < 4; j++)
#pragma unroll
                for (int c = 0; c < 4; c++)
                    mt_[((mt * 4 + j) * 4 + c) * 32] = acc[mt][j][c];
    }
    __syncthreads();

    const float scale = 1.0f / (float)(T_ * L_);
    float* ob = out + (size_t)b * L_ * L_;
    const bool mirror = (i_ != j_);
#pragma unroll
    for (int r = 0; r < 4; r++) {           // 4 x 256 = 1024 = 32x32 outputs
        const int o = tid + 256 * r;
        float s = 0.0f;
#pragma unroll
        for (int u = 0; u < 8; u++) s += mg[u * 1024 + o];
        s *= scale;

        // decode o -> (m_local, n_local) per the acc fragment layout
        const int lo = o & 31;
        const int gg = lo >> 2, qq = lo & 3;
        const int ii = o >> 5;               // 0..31
        const int cc = ii & 3, jj = (ii >> 2) & 3, mm = (ii >> 4) & 1;
        const int m = m0 + mm * 16 + gg + ((cc >> 1) << 3);
        const int n = n0 + jj * 8 + 2 * qq + (cc & 1);

        ob[(size_t)m * L_ + n] = s;
        if (mirror) ob[(size_t)n * L_ + m] = s;
    }
}

extern "C" void kernel_launch(void* const* d_in, const int* in_sizes, int n_in,
                              void* d_out, int out_size)
{
    const float* tgt = (const float*)d_in[0];
    float* out = (float*)d_out;

    cudaFuncSetAttribute(bispectrum_mma_kernel,
                         cudaFuncAttributeMaxDynamicSharedMemorySize, SM_TOTAL);

    bispectrum_mma_kernel<<<32 * 36, 256, SM_TOTAL>>>(tgt, out);

    // Reference returns (source, target): echo target after source if the
    // output buffer holds both.
    const long long src_elems = (long long)B_ * L_ * L_;        // 2,097,152
    const long long tgt_elems = (long long)B_ * T_ * L_;        // 65,536
    if ((long long)out_size >= src_elems + tgt_elems) {
        cudaMemcpyAsync(out + src_elems, tgt, sizeof(float) * tgt_elems,
                        cudaMemcpyDeviceToDevice);
    }
}